// round 14
// baseline (speedup 1.0000x reference)
#include <cuda_runtime.h>
#include <cuda_bf16.h>
#include <cuda_fp16.h>
#include <math.h>
#include <stdint.h>

#define EDIM  512
#define SEQ   1024
#define BATCH 2
#define NL    6
#define NH    3
#define VOCAB 32000
#define MROWS (BATCH*SEQ)
#define CATH  (NH*EDIM)
#define CATL  (NL*EDIM)
#define LHN   (NL*NH)

using bf16 = __nv_bfloat16;
using f16  = __half;

// ---------------- scratch ----------------------------------------------------
static __device__ float g_pvec[EDIM];
static __device__ float g_x   [MROWS*EDIM];
static __device__ f16   g_xf  [MROWS*EDIM];
static __device__ f16   g_WqTf[(size_t)LHN*EDIM*EDIM];
static __device__ f16   g_WkTf[(size_t)LHN*EDIM*EDIM];
static __device__ f16   g_WvTf[(size_t)LHN*EDIM*EDIM];
static __device__ f16   g_owTf[(size_t)VOCAB*CATL];
static __device__ f16   g_mwTf[(size_t)NL*EDIM*CATH];
static __device__ f16   g_qf  [(size_t)LHN*MROWS*EDIM];
static __device__ f16   g_kf  [(size_t)LHN*MROWS*EDIM];
static __device__ float g_vf  [(size_t)LHN*MROWS*EDIM];
static __device__ f16   g_vtf [(size_t)LHN*MROWS*EDIM];
static __device__ f16   g_pf  [(size_t)LHN*BATCH*SEQ*SEQ];
static __device__ f16   g_ocf [(size_t)NL*MROWS*CATH];
static __device__ float g_t1  [(size_t)NL*MROWS*EDIM];
static __device__ float g_a   [(size_t)NL*MROWS*EDIM];
static __device__ f16   g_af  [(size_t)NL*MROWS*EDIM];
static __device__ f16   g_catf[(size_t)MROWS*CATL];
static __device__ float g_w12 [(size_t)NL*EDIM*EDIM];
static __device__ float g_w123[(size_t)NL*EDIM*EDIM];
static __device__ f16   g_W123Tf[(size_t)NL*EDIM*EDIM];
static __device__ float g_bt  [NL*EDIM];
static __device__ float g_b123[NL*EDIM];

static __device__ f16* const g_f16_tab[5] = { g_WqTf, g_WkTf, g_WvTf, g_owTf, g_mwTf };

// ---------------- helpers -----------------------------------------------------
__device__ __forceinline__ uint32_t cvsm(const void* p) {
    return (uint32_t)__cvta_generic_to_shared(p);
}
__device__ __forceinline__ void cpa16(uint32_t saddr, const void* g) {
    asm volatile("cp.async.cg.shared.global [%0], [%1], 16;" :: "r"(saddr), "l"(g));
}
__device__ __forceinline__ void ldm4(uint32_t* r, uint32_t addr) {
    asm volatile("ldmatrix.sync.aligned.m8n8.x4.shared.b16 {%0,%1,%2,%3}, [%4];"
        : "=r"(r[0]), "=r"(r[1]), "=r"(r[2]), "=r"(r[3]) : "r"(addr));
}
__device__ __forceinline__ void mma_h(float* d, const uint32_t* a, uint32_t b0, uint32_t b1) {
    asm volatile("mma.sync.aligned.m16n8k16.row.col.f32.f16.f16.f32 "
        "{%0,%1,%2,%3}, {%4,%5,%6,%7}, {%8,%9}, {%0,%1,%2,%3};"
        : "+f"(d[0]), "+f"(d[1]), "+f"(d[2]), "+f"(d[3])
        : "r"(a[0]), "r"(a[1]), "r"(a[2]), "r"(a[3]), "r"(b0), "r"(b1));
}

// ---------------- fp16 single-product GEMM: C = alpha*A@B^T (+bias) ------------
// EPI 1: fp32. EPI 3: f16. EPI 4: f16 exp(v).
// Tile 128x128, BK=32 (two XOR-swizzled 4KB k16-subtiles per operand per stage),
// 8 warps (2M x 4N). K%32==0. 3 stages = 48KB static smem, single barrier per
// chunk: wait -> sync -> compute(2 subtiles) -> issue loads for c+2.
template<int EPI, bool SWAP>
__device__ __forceinline__ void mma_gemm(
    const uint16_t* __restrict__ Ah, int lda,
    const uint16_t* __restrict__ Bh, int ldb,
    int K, float alpha, const float* __restrict__ bias,
    float* __restrict__ Cf, void* __restrict__ C1, int ldc)
{
    constexpr int TILE = 4096;
    constexpr int STB  = 4*TILE;          // A0,A1,B0,B1
    __shared__ __align__(128) char smem[3 * STB];   // 49152 = 48KB
    const uint32_t sm0 = cvsm(smem);
    const int tid = threadIdx.x, lane = tid & 31, wid = tid >> 5;
    const int wm = wid & 1, wn = wid >> 1;
    const int bm = SWAP ? blockIdx.x : blockIdx.y;
    const int bn = SWAP ? blockIdx.y : blockIdx.x;
    const int mBase = bm * 128, nBase = bn * 128;

    const int crow = tid >> 1, cseg = tid & 1;
    const uint32_t cdst = (uint32_t)(crow * 32 + ((cseg ^ ((crow >> 2) & 1)) << 4));
    const uint16_t* gA0 = Ah + (size_t)(mBase + crow) * lda + cseg * 8;
    const uint16_t* gB0 = Bh + (size_t)(nBase + crow) * ldb + cseg * 8;

    const int lrow = lane & 15, kseg = lane >> 4;
    uint32_t offA[4], offB[2];
    #pragma unroll
    for (int mf = 0; mf < 4; ++mf) {
        int r = wm * 64 + mf * 16 + lrow;
        offA[mf] = (uint32_t)(r * 32 + ((kseg ^ ((r >> 2) & 1)) << 4));
    }
    #pragma unroll
    for (int j = 0; j < 2; ++j) {
        int r = wn * 32 + j * 16 + lrow;
        offB[j] = (uint32_t)(r * 32 + ((kseg ^ ((r >> 2) & 1)) << 4));
    }

    float acc[4][4][4];
    #pragma unroll
    for (int i = 0; i < 4; ++i)
        #pragma unroll
        for (int j = 0; j < 4; ++j)
            #pragma unroll
            for (int q = 0; q < 4; ++q) acc[i][j][q] = 0.f;

    const int nCh = K >> 5;
    #pragma unroll
    for (int p = 0; p < 2; ++p) {
        if (p < nCh) {
            const uint32_t sb = sm0 + (uint32_t)p * STB;
            const int ke = p << 5;
            cpa16(sb + cdst,          gA0 + ke);
            cpa16(sb + TILE + cdst,   gA0 + ke + 16);
            cpa16(sb + 2*TILE + cdst, gB0 + ke);
            cpa16(sb + 3*TILE + cdst, gB0 + ke + 16);
            asm volatile("cp.async.commit_group;");
        }
    }

    int stage = 0, lstage = 2;
    for (int c = 0; c < nCh; ++c) {
        if (c + 1 < nCh) asm volatile("cp.async.wait_group 1;");
        else             asm volatile("cp.async.wait_group 0;");
        __syncthreads();

        const uint32_t sb = sm0 + (uint32_t)stage * STB;
        #pragma unroll
        for (int kk = 0; kk < 2; ++kk) {
            const uint32_t ko = (uint32_t)kk * TILE;
            uint32_t ah[4][4], bh[2][4];
            #pragma unroll
            for (int mf = 0; mf < 4; ++mf) ldm4(ah[mf], sb + ko + offA[mf]);
            #pragma unroll
            for (int j = 0; j < 2; ++j) ldm4(bh[j], sb + 2*TILE + ko + offB[j]);
            #pragma unroll
            for (int mf = 0; mf < 4; ++mf) {
                #pragma unroll
                for (int j = 0; j < 2; ++j) {
                    mma_h(acc[mf][2*j],   ah[mf], bh[j][0], bh[j][2]);
                    mma_h(acc[mf][2*j+1], ah[mf], bh[j][1], bh[j][3]);
                }
            }
        }

        if (c + 2 < nCh) {
            const uint32_t sb2 = sm0 + (uint32_t)lstage * STB;
            const int ke = (c + 2) << 5;
            cpa16(sb2 + cdst,          gA0 + ke);
            cpa16(sb2 + TILE + cdst,   gA0 + ke + 16);
            cpa16(sb2 + 2*TILE + cdst, gB0 + ke);
            cpa16(sb2 + 3*TILE + cdst, gB0 + ke + 16);
            asm volatile("cp.async.commit_group;");
        }
        if (++stage == 3) stage = 0;
        if (++lstage == 3) lstage = 0;
    }

    const int g = lane >> 2, t = lane & 3;
    #pragma unroll
    for (int nb = 0; nb < 4; ++nb) {
        const int col = nBase + wn * 32 + nb * 8 + t * 2;
        float b0 = 0.f, b1 = 0.f;
        if (bias) { b0 = bias[col]; b1 = bias[col + 1]; }
        #pragma unroll
        for (int mf = 0; mf < 4; ++mf) {
            const int row0 = mBase + wm * 64 + mf * 16 + g;
            float v0 = fmaf(alpha, acc[mf][nb][0], b0);
            float v1 = fmaf(alpha, acc[mf][nb][1], b1);
            float v2 = fmaf(alpha, acc[mf][nb][2], b0);
            float v3 = fmaf(alpha, acc[mf][nb][3], b1);
            const size_t gidx  = (size_t)row0 * ldc + col;
            const size_t gidx2 = (size_t)(row0 + 8) * ldc + col;
            if (EPI == 1) {
                float2 p0; p0.x = v0; p0.y = v1;
                float2 p1; p1.x = v2; p1.y = v3;
                *reinterpret_cast<float2*>(Cf + gidx)  = p0;
                *reinterpret_cast<float2*>(Cf + gidx2) = p1;
            } else if (EPI == 3) {
                f16* Chf = (f16*)C1;
                __half2 p0 = __floats2half2_rn(v0, v1);
                __half2 p1 = __floats2half2_rn(v2, v3);
                *reinterpret_cast<__half2*>(Chf + gidx)  = p0;
                *reinterpret_cast<__half2*>(Chf + gidx2) = p1;
            } else {
                f16* Chf = (f16*)C1;
                __half2 p0 = __floats2half2_rn(__expf(v0), __expf(v1));
                __half2 p1 = __floats2half2_rn(__expf(v2), __expf(v3));
                *reinterpret_cast<__half2*>(Chf + gidx)  = p0;
                *reinterpret_cast<__half2*>(Chf + gidx2) = p1;
            }
        }
    }
}

// ---------------- GEMM wrapper kernels -----------------------------------------
__global__ __launch_bounds__(256,2) void tc_qkv() {
    int z = blockIdx.z;
    int which = z / LHN;
    size_t lh = z % LHN;
    const uint16_t* A = (const uint16_t*)g_xf;
    if (which == 0) {
        mma_gemm<3,false>(A, EDIM, (const uint16_t*)(g_WqTf + lh*EDIM*EDIM), EDIM,
            EDIM, 1.f, nullptr, nullptr, g_qf + lh*(size_t)MROWS*EDIM, EDIM);
    } else if (which == 1) {
        mma_gemm<3,false>(A, EDIM, (const uint16_t*)(g_WkTf + lh*EDIM*EDIM), EDIM,
            EDIM, 1.f, nullptr, nullptr, g_kf + lh*(size_t)MROWS*EDIM, EDIM);
    } else {
        mma_gemm<1,false>(A, EDIM, (const uint16_t*)(g_WvTf + lh*EDIM*EDIM), EDIM,
            EDIM, 1.f, nullptr, g_vf + lh*(size_t)MROWS*EDIM, nullptr, EDIM);
    }
}
__global__ __launch_bounds__(256,2) void tc_score() {
    if (blockIdx.y > blockIdx.x) return;
    size_t z = blockIdx.z;
    size_t off = z * (size_t)SEQ * EDIM;
    mma_gemm<4,false>((const uint16_t*)(g_qf + off), EDIM,
        (const uint16_t*)(g_kf + off), EDIM,
        EDIM, 0.044194173824159216f, nullptr,
        nullptr, g_pf + z*(size_t)SEQ*SEQ, SEQ);
}
__global__ __launch_bounds__(256,2) void tc_attnout() {
    size_t z = blockIdx.z;
    size_t lh = z >> 1, b = z & 1;
    size_t l = lh / NH, h = lh % NH;
    size_t coff = l*(size_t)MROWS*CATH + b*(size_t)SEQ*CATH + h*EDIM;
    const int kBeg = blockIdx.y * 128;
    mma_gemm<3,false>((const uint16_t*)(g_pf + z*(size_t)SEQ*SEQ + kBeg), SEQ,
        (const uint16_t*)(g_vtf + z*(size_t)EDIM*SEQ + kBeg), SEQ,
        SEQ - kBeg, 1.f, nullptr, nullptr, g_ocf + coff, CATH);
}
__global__ __launch_bounds__(256,2) void tc_mh() {
    size_t l = blockIdx.z;
    mma_gemm<1,false>((const uint16_t*)(g_ocf + l*(size_t)MROWS*CATH), CATH,
        (const uint16_t*)(g_mwTf + l*(size_t)EDIM*CATH), CATH,
        CATH, 1.f, nullptr, g_t1 + l*(size_t)MROWS*EDIM, nullptr, EDIM);
}
__global__ __launch_bounds__(256,2) void tc_lin() {
    size_t l = blockIdx.z;
    mma_gemm<1,false>((const uint16_t*)(g_af + l*(size_t)MROWS*EDIM), EDIM,
        (const uint16_t*)(g_W123Tf + l*(size_t)EDIM*EDIM), EDIM,
        EDIM, 1.f, g_b123 + l*EDIM, g_t1 + l*(size_t)MROWS*EDIM, nullptr, EDIM);
}
__global__ __launch_bounds__(256,2) void tc_final(const float* __restrict__ bias,
                                                  float* __restrict__ out) {
    mma_gemm<1,true>((const uint16_t*)g_catf, CATL,
        (const uint16_t*)g_owTf, CATL,
        CATL, 1.f, bias, out, nullptr, VOCAB);
}

// ---------------- fp32 SGEMM (for W123 precompute) ------------------------------
__device__ __forceinline__ float4 ld4(const float* p) {
    return *reinterpret_cast<const float4*>(p);
}
__device__ void sgemm_core(const float* __restrict__ A, int lda,
                           const float* __restrict__ B, int ldb,
                           float* __restrict__ C, int ldc, int K)
{
    __shared__ float As[8][128];
    __shared__ float Bs[8][128];
    const int tid = threadIdx.x;
    const int tx = tid & 15, ty = tid >> 4;
    const int lRow = tid >> 1, lCol = (tid & 1) << 2;
    const int bRow = tid >> 5, bCol = (tid & 31) << 2;
    const int bm = blockIdx.y, bn = blockIdx.x;
    const float* Ab = A + (size_t)bm * 128 * lda;
    const float* Bb = B + bn * 128;
    float acc[8][8];
    #pragma unroll
    for (int i = 0; i < 8; i++)
        #pragma unroll
        for (int j = 0; j < 8; j++) acc[i][j] = 0.f;
    for (int k0 = 0; k0 < K; k0 += 8) {
        float4 av = ld4(Ab + (size_t)lRow * lda + k0 + lCol);
        As[lCol+0][lRow] = av.x; As[lCol+1][lRow] = av.y;
        As[lCol+2][lRow] = av.z; As[lCol+3][lRow] = av.w;
        float4 bv = ld4(Bb + (size_t)(k0 + bRow) * ldb + bCol);
        *reinterpret_cast<float4*>(&Bs[bRow][bCol]) = bv;
        __syncthreads();
        #pragma unroll
        for (int kk = 0; kk < 8; kk++) {
            float4 a0 = ld4(&As[kk][ty*4]);
            float4 a1 = ld4(&As[kk][64 + ty*4]);
            float4 b0 = ld4(&Bs[kk][tx*4]);
            float4 b1 = ld4(&Bs[kk][64 + tx*4]);
            float ar[8] = {a0.x,a0.y,a0.z,a0.w, a1.x,a1.y,a1.z,a1.w};
            float br[8] = {b0.x,b0.y,b0.z,b0.w, b1.x,b1.y,b1.z,b1.w};
            #pragma unroll
            for (int i = 0; i < 8; i++)
                #pragma unroll
                for (int j = 0; j < 8; j++)
                    acc[i][j] = fmaf(ar[i], br[j], acc[i][j]);
        }
        __syncthreads();
    }
    #pragma unroll
    for (int i = 0; i < 8; i++) {
        int rloc = (i < 4) ? (ty*4 + i) : (64 + ty*4 + (i-4));
        size_t row = (size_t)bm * 128 + rloc;
        #pragma unroll
        for (int jh = 0; jh < 2; jh++) {
            int cloc = (jh == 0) ? (tx*4) : (64 + tx*4);
            int col = bn * 128 + cloc;
            float4 r;
            r.x = acc[i][jh*4+0]; r.y = acc[i][jh*4+1];
            r.z = acc[i][jh*4+2]; r.w = acc[i][jh*4+3];
            *reinterpret_cast<float4*>(&C[row * ldc + col]) = r;
        }
    }
}
__global__ __launch_bounds__(256) void k_w12(const float* __restrict__ w1,
                                             const float* __restrict__ w2) {
    size_t l = blockIdx.z;
    sgemm_core(w1 + l*EDIM*EDIM, EDIM, w2 + l*EDIM*EDIM, EDIM,
               g_w12 + l*EDIM*EDIM, EDIM, EDIM);
}
__global__ __launch_bounds__(256) void k_w123(const float* __restrict__ w3) {
    size_t l = blockIdx.z;
    sgemm_core(g_w12 + l*EDIM*EDIM, EDIM, w3 + l*EDIM*EDIM, EDIM,
               g_w123 + l*EDIM*EDIM, EDIM, EDIM);
}
__global__ void k_bfold1(const float* __restrict__ b1, const float* __restrict__ w2,
                         const float* __restrict__ b2) {
    int l = blockIdx.x, j = threadIdx.x;
    float s = b2[l*EDIM + j];
    const float* w = w2 + (size_t)l*EDIM*EDIM;
    const float* b = b1 + l*EDIM;
    for (int i = 0; i < EDIM; i++) s = fmaf(b[i], w[(size_t)i*EDIM + j], s);
    g_bt[l*EDIM + j] = s;
}
__global__ void k_bfold2(const float* __restrict__ w3, const float* __restrict__ b3) {
    int l = blockIdx.x, j = threadIdx.x;
    float s = b3[l*EDIM + j];
    const float* w = w3 + (size_t)l*EDIM*EDIM;
    const float* b = g_bt + l*EDIM;
    for (int i = 0; i < EDIM; i++) s = fmaf(b[i], w[(size_t)i*EDIM + j], s);
    g_b123[l*EDIM + j] = s;
}

// ---------------- small kernels --------------------------------------------------
__global__ void k_pvec() {
    int i = threadIdx.x;
    if (i < EDIM) {
        double denom = pow(10000.0, 2.0 * (double)i / (double)EDIM);
        double arg = (double)(SEQ - 1) / denom;
        g_pvec[i] = (i % 2 == 0) ? (float)sin(arg) : (float)cos(arg);
    }
}
__global__ void k_embed(const int* __restrict__ inputs, const float* __restrict__ emb) {
    int row = blockIdx.x;
    int idx = inputs[row];
    const float* src = emb + (size_t)idx * EDIM;
    for (int i = threadIdx.x; i < EDIM; i += blockDim.x) {
        float v = src[i] + g_pvec[i];
        g_x[(size_t)row * EDIM + i] = v;
        g_xf[(size_t)row * EDIM + i] = __float2half_rn(v);
    }
}
// warp-coalesced 64x64 transpose-convert: fp32 [R,C] (harness ptr) -> f16 [C,R]
__global__ __launch_bounds__(256) void k_tconvW(const float* __restrict__ in,
                                                int slot, int R, int C) {
    __shared__ float s[64][65];
    f16* out = g_f16_tab[slot];
    size_t zo = (size_t)blockIdx.z * ((size_t)R * C);
    int c0 = blockIdx.x * 64, r0 = blockIdx.y * 64;
    int tid = threadIdx.x;
    #pragma unroll
    for (int p = 0; p < 4; p++) {
        int idx = tid + p * 256;
        int r = idx >> 4, cs = (idx & 15) * 4;
        float4 v = *reinterpret_cast<const float4*>(in + zo + (size_t)(r0 + r) * C + c0 + cs);
        s[r][cs] = v.x; s[r][cs+1] = v.y; s[r][cs+2] = v.z; s[r][cs+3] = v.w;
    }
    __syncthreads();
    int w = tid >> 5, lane = tid & 31;
    #pragma unroll
    for (int i = 0; i < 8; i++) {
        int n = w * 8 + i;
        __half2 h = __floats2half2_rn(s[lane * 2][n], s[lane * 2 + 1][n]);
        *reinterpret_cast<__half2*>(out + zo + (size_t)(c0 + n) * R + r0 + lane * 2) = h;
    }
}
// g_vf -> g_vtf (R=SEQ, C=EDIM)
__global__ __launch_bounds__(256) void k_tconvW_v() {
    __shared__ float s[64][65];
    size_t zo = (size_t)blockIdx.z * SEQ * EDIM;
    int c0 = blockIdx.x * 64, r0 = blockIdx.y * 64;
    int tid = threadIdx.x;
    #pragma unroll
    for (int p = 0; p < 4; p++) {
        int idx = tid + p * 256;
        int r = idx >> 4, cs = (idx & 15) * 4;
        float4 v = *reinterpret_cast<const float4*>(g_vf + zo + (size_t)(r0 + r) * EDIM + c0 + cs);
        s[r][cs] = v.x; s[r][cs+1] = v.y; s[r][cs+2] = v.z; s[r][cs+3] = v.w;
    }
    __syncthreads();
    int w = tid >> 5, lane = tid & 31;
    #pragma unroll
    for (int i = 0; i < 8; i++) {
        int n = w * 8 + i;
        __half2 h = __floats2half2_rn(s[lane * 2][n], s[lane * 2 + 1][n]);
        *reinterpret_cast<__half2*>(g_vtf + zo + (size_t)(c0 + n) * SEQ + r0 + lane * 2) = h;
    }
}
// g_w123 -> g_W123Tf
__global__ __launch_bounds__(256) void k_tconvW_123() {
    __shared__ float s[64][65];
    size_t zo = (size_t)blockIdx.z * EDIM * EDIM;
    int c0 = blockIdx.x * 64, r0 = blockIdx.y * 64;
    int tid = threadIdx.x;
    #pragma unroll
    for (int p = 0; p < 4; p++) {
        int idx = tid + p * 256;
        int r = idx >> 4, cs = (idx & 15) * 4;
        float4 v = *reinterpret_cast<const float4*>(g_w123 + zo + (size_t)(r0 + r) * EDIM + c0 + cs);
        s[r][cs] = v.x; s[r][cs+1] = v.y; s[r][cs+2] = v.z; s[r][cs+3] = v.w;
    }
    __syncthreads();
    int w = tid >> 5, lane = tid & 31;
    #pragma unroll
    for (int i = 0; i < 8; i++) {
        int n = w * 8 + i;
        __half2 h = __floats2half2_rn(s[lane * 2][n], s[lane * 2 + 1][n]);
        *reinterpret_cast<__half2*>(g_W123Tf + zo + (size_t)(c0 + n) * EDIM + r0 + lane * 2) = h;
    }
}
// column softmax over query axis s (masked s<=t) on f16 exp values, in place
__global__ void k_softmax() {
    size_t z = blockIdx.y;
    int t0 = (blockIdx.x * blockDim.x + threadIdx.x) * 2;
    f16* pf = g_pf + z * (size_t)SEQ * SEQ;
    float s0 = 0.f, s1 = 0.f;
    for (int s = 0; s <= t0 + 1; s++) {
        __half2 e = *reinterpret_cast<__half2*>(pf + (size_t)s * SEQ + t0);
        float2 ef = __half22float2(e);
        if (s <= t0) s0 += ef.x;
        s1 += ef.y;
    }
    float i0 = 1.f / s0, i1 = 1.f / s1;
    for (int s = 0; s < SEQ; s++) {
        __half2 e = *reinterpret_cast<__half2*>(pf + (size_t)s * SEQ + t0);
        float2 ef = __half22float2(e);
        float p0 = (s <= t0)     ? ef.x * i0 : 0.f;
        float p1 = (s <= t0 + 1) ? ef.y * i1 : 0.f;
        *reinterpret_cast<__half2*>(pf + (size_t)s * SEQ + t0) = __floats2half2_rn(p0, p1);
    }
}
__device__ __forceinline__ float block_reduce128(float v) {
    __shared__ float sh[4];
    #pragma unroll
    for (int o = 16; o > 0; o >>= 1) v += __shfl_down_sync(0xffffffffu, v, o);
    int lane = threadIdx.x & 31, w = threadIdx.x >> 5;
    if (lane == 0) sh[w] = v;
    __syncthreads();
    float r = sh[0] + sh[1] + sh[2] + sh[3];
    __syncthreads();
    return r;
}
__global__ void k_ln_a(const float* __restrict__ mh_b, const float* __restrict__ ln_g,
                       const float* __restrict__ ln_b) {
    int l = blockIdx.y;
    size_t row = blockIdx.x;
    const float* xr = g_x + row * EDIM;
    const float* tr = g_t1 + ((size_t)l * MROWS + row) * EDIM;
    const float* mb = mh_b + (size_t)l * EDIM;
    int base = threadIdx.x * 4;
    float v[4]; float s = 0.f;
    #pragma unroll
    for (int j = 0; j < 4; j++) { v[j] = xr[base+j] + tr[base+j] + mb[base+j]; s += v[j]; }
    float mean = block_reduce128(s) * (1.f / EDIM);
    float s2 = 0.f;
    #pragma unroll
    for (int j = 0; j < 4; j++) { float d = v[j] - mean; s2 += d * d; }
    float var = block_reduce128(s2) * (1.f / EDIM);
    float inv = rsqrtf(var + 1e-5f);
    const float* g = ln_g + (size_t)l * EDIM;
    const float* b = ln_b + (size_t)l * EDIM;
    size_t o = ((size_t)l * MROWS + row) * EDIM + base;
    #pragma unroll
    for (int j = 0; j < 4; j++) {
        float r = (v[j] - mean) * inv * g[base+j] + b[base+j];
        g_a[o+j] = r;
        g_af[o+j] = __float2half_rn(r);
    }
}
__global__ void k_ln_cat(const float* __restrict__ ln_g, const float* __restrict__ ln_b) {
    int l = blockIdx.y;
    size_t row = blockIdx.x;
    const float* tr = g_t1 + ((size_t)l * MROWS + row) * EDIM;
    const float* ar = g_a + ((size_t)l * MROWS + row) * EDIM;
    int base = threadIdx.x * 4;
    float v[4]; float s = 0.f;
    #pragma unroll
    for (int j = 0; j < 4; j++) { v[j] = tr[base+j] + ar[base+j]; s += v[j]; }
    float mean = block_reduce128(s) * (1.f / EDIM);
    float s2 = 0.f;
    #pragma unroll
    for (int j = 0; j < 4; j++) { float d = v[j] - mean; s2 += d * d; }
    float var = block_reduce128(s2) * (1.f / EDIM);
    float inv = rsqrtf(var + 1e-5f);
    const float* g = ln_g + (size_t)l * EDIM;
    const float* b = ln_b + (size_t)l * EDIM;
    size_t o = row * CATL + (size_t)l * EDIM + base;
    #pragma unroll
    for (int j = 0; j < 4; j++) {
        float r = (v[j] - mean) * inv * g[base+j] + b[base+j];
        g_catf[o+j] = __float2half_rn(r);
    }
}

// ---------------- launch ----------------------------------------------------------
extern "C" void kernel_launch(void* const* d_in, const int* in_sizes, int n_in,
                              void* d_out, int out_size) {
    (void)n_in; (void)out_size;
    const int*   inputs = (const int*)d_in[0];
    const float* emb_w  = (const float*)d_in[1];
    const float* Wq     = (const float*)d_in[2];
    const float* Wk     = (const float*)d_in[3];
    const float* Wv     = (const float*)d_in[4];
    const float *mh_w, *mh_b;
    if (in_sizes[5] == NL * EDIM) { mh_b = (const float*)d_in[5]; mh_w = (const float*)d_in[6]; }
    else                          { mh_w = (const float*)d_in[5]; mh_b = (const float*)d_in[6]; }
    const float* l1_w = (const float*)d_in[7];
    const float* l1_b = (const float*)d_in[8];
    const float* l2_w = (const float*)d_in[9];
    const float* l2_b = (const float*)d_in[10];
    const float* l3_w = (const float*)d_in[11];
    const float* l3_b = (const float*)d_in[12];
    const float* ln_g = (const float*)d_in[13];
    const float* ln_b = (const float*)d_in[14];
    const float* out_w = (const float*)d_in[15];
    const float* out_b = (const float*)d_in[16];
    float* out = (float*)d_out;

    k_pvec<<<1, 512>>>();
    k_embed<<<MROWS, 128>>>(inputs, emb_w);
    k_tconvW<<<dim3(EDIM/64, EDIM/64, LHN), 256>>>(Wq, 0, EDIM, EDIM);
    k_tconvW<<<dim3(EDIM/64, EDIM/64, LHN), 256>>>(Wk, 1, EDIM, EDIM);
    k_tconvW<<<dim3(EDIM/64, EDIM/64, LHN), 256>>>(Wv, 2, EDIM, EDIM);
    tc_qkv<<<dim3(EDIM/128, MROWS/128, 3*LHN), 256>>>();
    k_tconvW_v<<<dim3(EDIM/64, SEQ/64, LHN*BATCH), 256>>>();
    tc_score<<<dim3(SEQ/128, SEQ/128, LHN*BATCH), 256>>>();
    k_softmax<<<dim3(SEQ/256, LHN*BATCH), 128>>>();
    tc_attnout<<<dim3(EDIM/128, SEQ/128, LHN*BATCH), 256>>>();
    k_tconvW<<<dim3(EDIM/64, CATH/64, NL), 256>>>(mh_w, 4, CATH, EDIM);
    tc_mh<<<dim3(EDIM/128, MROWS/128, NL), 256>>>();
    k_ln_a<<<dim3(MROWS, NL), 128>>>(mh_b, ln_g, ln_b);
    k_w12<<<dim3(4,4,NL), 256>>>(l1_w, l2_w);
    k_w123<<<dim3(4,4,NL), 256>>>(l3_w);
    k_bfold1<<<NL, EDIM>>>(l1_b, l2_w, l2_b);
    k_bfold2<<<NL, EDIM>>>(l3_w, l3_b);
    k_tconvW_123<<<dim3(EDIM/64, EDIM/64, NL), 256>>>();
    tc_lin<<<dim3(EDIM/128, MROWS/128, NL), 256>>>();
    k_ln_cat<<<dim3(MROWS, NL), 128>>>(ln_g, ln_b);
    k_tconvW<<<dim3(VOCAB/64, CATL/64, 1), 256>>>(out_w, 3, CATL, VOCAB);
    tc_final<<<dim3(MROWS/128, VOCAB/128, 1), 256>>>(out_b, out);
}

// round 15
// speedup vs baseline: 1.0862x; 1.0862x over previous
#include <cuda_runtime.h>
#include <cuda_bf16.h>
#include <cuda_fp16.h>
#include <math.h>
#include <stdint.h>

#define EDIM  512
#define SEQ   1024
#define BATCH 2
#define NL    6
#define NH    3
#define VOCAB 32000
#define MROWS (BATCH*SEQ)
#define CATH  (NH*EDIM)
#define CATL  (NL*EDIM)
#define LHN   (NL*NH)

using bf16 = __nv_bfloat16;
using f16  = __half;

// ---------------- scratch ----------------------------------------------------
static __device__ float g_pvec[EDIM];
static __device__ float g_x   [MROWS*EDIM];
static __device__ f16   g_xf  [MROWS*EDIM];
static __device__ f16   g_WqTf[(size_t)LHN*EDIM*EDIM];
static __device__ f16   g_WkTf[(size_t)LHN*EDIM*EDIM];
static __device__ f16   g_WvTf[(size_t)LHN*EDIM*EDIM];
static __device__ f16   g_owTf[(size_t)VOCAB*CATL];   // [CATL, VOCAB] k-major (BT path)
static __device__ f16   g_mwTf[(size_t)NL*EDIM*CATH];
static __device__ f16   g_qf  [(size_t)LHN*MROWS*EDIM];
static __device__ f16   g_kf  [(size_t)LHN*MROWS*EDIM];
static __device__ float g_vf  [(size_t)LHN*MROWS*EDIM];
static __device__ f16   g_vtf [(size_t)LHN*MROWS*EDIM];
static __device__ f16   g_pf  [(size_t)LHN*BATCH*SEQ*SEQ];
static __device__ f16   g_ocf [(size_t)NL*MROWS*CATH];
static __device__ float g_t1  [(size_t)NL*MROWS*EDIM];
static __device__ float g_a   [(size_t)NL*MROWS*EDIM];
static __device__ f16   g_af  [(size_t)NL*MROWS*EDIM];
static __device__ f16   g_catf[(size_t)MROWS*CATL];
static __device__ float g_w12 [(size_t)NL*EDIM*EDIM];
static __device__ float g_w123[(size_t)NL*EDIM*EDIM];
static __device__ f16   g_W123Tf[(size_t)NL*EDIM*EDIM];
static __device__ float g_bt  [NL*EDIM];
static __device__ float g_b123[NL*EDIM];

static __device__ f16* const g_f16_tab[5] = { g_WqTf, g_WkTf, g_WvTf, g_owTf, g_mwTf };

// ---------------- helpers -----------------------------------------------------
__device__ __forceinline__ uint32_t cvsm(const void* p) {
    return (uint32_t)__cvta_generic_to_shared(p);
}
__device__ __forceinline__ void cpa16(uint32_t saddr, const void* g) {
    asm volatile("cp.async.cg.shared.global [%0], [%1], 16;" :: "r"(saddr), "l"(g));
}
__device__ __forceinline__ void ldm4(uint32_t* r, uint32_t addr) {
    asm volatile("ldmatrix.sync.aligned.m8n8.x4.shared.b16 {%0,%1,%2,%3}, [%4];"
        : "=r"(r[0]), "=r"(r[1]), "=r"(r[2]), "=r"(r[3]) : "r"(addr));
}
__device__ __forceinline__ void ldm4t(uint32_t* r, uint32_t addr) {
    asm volatile("ldmatrix.sync.aligned.m8n8.x4.trans.shared.b16 {%0,%1,%2,%3}, [%4];"
        : "=r"(r[0]), "=r"(r[1]), "=r"(r[2]), "=r"(r[3]) : "r"(addr));
}
__device__ __forceinline__ void mma_h(float* d, const uint32_t* a, uint32_t b0, uint32_t b1) {
    asm volatile("mma.sync.aligned.m16n8k16.row.col.f32.f16.f16.f32 "
        "{%0,%1,%2,%3}, {%4,%5,%6,%7}, {%8,%9}, {%0,%1,%2,%3};"
        : "+f"(d[0]), "+f"(d[1]), "+f"(d[2]), "+f"(d[3])
        : "r"(a[0]), "r"(a[1]), "r"(a[2]), "r"(a[3]), "r"(b0), "r"(b1));
}

// ---------------- fp16 single-product GEMM: C = alpha*A@B^T (+bias) ------------
// EPI 1: fp32. EPI 3: f16. EPI 4: f16 exp(v).
// BT=false: B stored [N,K] row-major (proven path).
// BT=true : B stored [K,N] row-major; B tiles are 16xBN k-major, loaded with
//           ldmatrix.trans (fragment identical to the BT=false path).
// Tile 128x128, BK=16, 8 warps (2M x 4N). 3-stage pipeline, single barrier:
// wait -> sync -> compute -> issue loads for c+2.
template<int EPI, bool SWAP, bool BT>
__device__ __forceinline__ void mma_gemm(
    const uint16_t* __restrict__ Ah, int lda,
    const uint16_t* __restrict__ Bh, int ldb,
    int K, float alpha, const float* __restrict__ bias,
    float* __restrict__ Cf, void* __restrict__ C1, int ldc)
{
    constexpr int TILE = 4096;
    constexpr int STB  = 2*TILE;
    __shared__ __align__(128) char smem[3 * STB];
    const uint32_t sm0 = cvsm(smem);
    const int tid = threadIdx.x, lane = tid & 31, wid = tid >> 5;
    const int wm = wid & 1, wn = wid >> 1;
    const int bm = SWAP ? blockIdx.x : blockIdx.y;
    const int bn = SWAP ? blockIdx.y : blockIdx.x;
    const int mBase = bm * 128, nBase = bn * 128;

    // A cp.async mapping (always [M,K] 128x16 tile, XOR swizzle)
    const int crow = tid >> 1, cseg = tid & 1;
    const uint32_t cdstA = (uint32_t)(crow * 32 + ((cseg ^ ((crow >> 2) & 1)) << 4));
    const uint16_t* gA0 = Ah + (size_t)(mBase + crow) * lda + cseg * 8;

    // B cp.async mapping
    uint32_t cdstB;
    const uint16_t* gB0;
    if (BT) {
        // [K,N] tile: 16 k-rows x 128 n (256B/row); granule swizzle seg^(k&7)
        const int krow = tid >> 4, seg = tid & 15;
        cdstB = (uint32_t)(krow * 256 + ((seg ^ (krow & 7)) << 4));
        gB0 = Bh + (size_t)krow * ldb + nBase + seg * 8;
    } else {
        cdstB = cdstA;
        gB0 = Bh + (size_t)(nBase + crow) * ldb + cseg * 8;
    }

    const int lrow = lane & 15, kseg = lane >> 4;
    uint32_t offA[4], offB[2];
    #pragma unroll
    for (int mf = 0; mf < 4; ++mf) {
        int r = wm * 64 + mf * 16 + lrow;
        offA[mf] = (uint32_t)(r * 32 + ((kseg ^ ((r >> 2) & 1)) << 4));
    }
    if (BT) {
        // lanes 0-7: m0=(k0-7, n0-7); 8-15: m1=(k0-7, n8-15);
        // 16-23: m2=(k8-15, n0-7); 24-31: m3=(k8-15, n8-15)
        const int kk = (lane & 7) | ((lane & 16) >> 1);      // k row 0-15
        const int nb = (lane >> 3) & 1;                       // n8 half
        #pragma unroll
        for (int j = 0; j < 2; ++j) {
            int gb = wn * 4 + j * 2 + nb;                     // 16B granule along n
            offB[j] = (uint32_t)(kk * 256 + ((gb ^ (kk & 7)) << 4));
        }
    } else {
        #pragma unroll
        for (int j = 0; j < 2; ++j) {
            int r = wn * 32 + j * 16 + lrow;
            offB[j] = (uint32_t)(r * 32 + ((kseg ^ ((r >> 2) & 1)) << 4));
        }
    }

    float acc[4][4][4];
    #pragma unroll
    for (int i = 0; i < 4; ++i)
        #pragma unroll
        for (int j = 0; j < 4; ++j)
            #pragma unroll
            for (int q = 0; q < 4; ++q) acc[i][j][q] = 0.f;

    const int nCh = K >> 4;
    #pragma unroll
    for (int p = 0; p < 2; ++p) {
        if (p < nCh) {
            const uint32_t sb = sm0 + (uint32_t)p * STB;
            const int ke = p << 4;
            cpa16(sb + cdstA, gA0 + ke);
            cpa16(sb + TILE + cdstB, gB0 + (BT ? (size_t)ke * ldb : (size_t)ke));
            asm volatile("cp.async.commit_group;");
        }
    }

    int stage = 0, lstage = 2;
    for (int c = 0; c < nCh; ++c) {
        if (c + 1 < nCh) asm volatile("cp.async.wait_group 1;");
        else             asm volatile("cp.async.wait_group 0;");
        __syncthreads();

        const uint32_t sb = sm0 + (uint32_t)stage * STB;
        uint32_t ah[4][4], bh[2][4];
        #pragma unroll
        for (int mf = 0; mf < 4; ++mf) ldm4(ah[mf], sb + offA[mf]);
        #pragma unroll
        for (int j = 0; j < 2; ++j) {
            if (BT) ldm4t(bh[j], sb + TILE + offB[j]);
            else    ldm4 (bh[j], sb + TILE + offB[j]);
        }
        #pragma unroll
        for (int mf = 0; mf < 4; ++mf) {
            #pragma unroll
            for (int j = 0; j < 2; ++j) {
                mma_h(acc[mf][2*j],   ah[mf], bh[j][0], bh[j][2]);
                mma_h(acc[mf][2*j+1], ah[mf], bh[j][1], bh[j][3]);
            }
        }

        if (c + 2 < nCh) {
            const uint32_t sb2 = sm0 + (uint32_t)lstage * STB;
            const int ke = (c + 2) << 4;
            cpa16(sb2 + cdstA, gA0 + ke);
            cpa16(sb2 + TILE + cdstB, gB0 + (BT ? (size_t)ke * ldb : (size_t)ke));
            asm volatile("cp.async.commit_group;");
        }
        if (++stage == 3) stage = 0;
        if (++lstage == 3) lstage = 0;
    }

    const int g = lane >> 2, t = lane & 3;
    #pragma unroll
    for (int nb = 0; nb < 4; ++nb) {
        const int col = nBase + wn * 32 + nb * 8 + t * 2;
        float b0 = 0.f, b1 = 0.f;
        if (bias) { b0 = bias[col]; b1 = bias[col + 1]; }
        #pragma unroll
        for (int mf = 0; mf < 4; ++mf) {
            const int row0 = mBase + wm * 64 + mf * 16 + g;
            float v0 = fmaf(alpha, acc[mf][nb][0], b0);
            float v1 = fmaf(alpha, acc[mf][nb][1], b1);
            float v2 = fmaf(alpha, acc[mf][nb][2], b0);
            float v3 = fmaf(alpha, acc[mf][nb][3], b1);
            const size_t gidx  = (size_t)row0 * ldc + col;
            const size_t gidx2 = (size_t)(row0 + 8) * ldc + col;
            if (EPI == 1) {
                float2 p0; p0.x = v0; p0.y = v1;
                float2 p1; p1.x = v2; p1.y = v3;
                *reinterpret_cast<float2*>(Cf + gidx)  = p0;
                *reinterpret_cast<float2*>(Cf + gidx2) = p1;
            } else if (EPI == 3) {
                f16* Chf = (f16*)C1;
                __half2 p0 = __floats2half2_rn(v0, v1);
                __half2 p1 = __floats2half2_rn(v2, v3);
                *reinterpret_cast<__half2*>(Chf + gidx)  = p0;
                *reinterpret_cast<__half2*>(Chf + gidx2) = p1;
            } else {
                f16* Chf = (f16*)C1;
                __half2 p0 = __floats2half2_rn(__expf(v0), __expf(v1));
                __half2 p1 = __floats2half2_rn(__expf(v2), __expf(v3));
                *reinterpret_cast<__half2*>(Chf + gidx)  = p0;
                *reinterpret_cast<__half2*>(Chf + gidx2) = p1;
            }
        }
    }
}

// ---------------- GEMM wrapper kernels -----------------------------------------
__global__ __launch_bounds__(256,2) void tc_qkv() {
    int z = blockIdx.z;
    int which = z / LHN;
    size_t lh = z % LHN;
    const uint16_t* A = (const uint16_t*)g_xf;
    if (which == 0) {
        mma_gemm<3,false,false>(A, EDIM, (const uint16_t*)(g_WqTf + lh*EDIM*EDIM), EDIM,
            EDIM, 1.f, nullptr, nullptr, g_qf + lh*(size_t)MROWS*EDIM, EDIM);
    } else if (which == 1) {
        mma_gemm<3,false,false>(A, EDIM, (const uint16_t*)(g_WkTf + lh*EDIM*EDIM), EDIM,
            EDIM, 1.f, nullptr, nullptr, g_kf + lh*(size_t)MROWS*EDIM, EDIM);
    } else {
        mma_gemm<1,false,false>(A, EDIM, (const uint16_t*)(g_WvTf + lh*EDIM*EDIM), EDIM,
            EDIM, 1.f, nullptr, g_vf + lh*(size_t)MROWS*EDIM, nullptr, EDIM);
    }
}
__global__ __launch_bounds__(256,2) void tc_score() {
    if (blockIdx.y > blockIdx.x) return;
    size_t z = blockIdx.z;
    size_t off = z * (size_t)SEQ * EDIM;
    mma_gemm<4,false,false>((const uint16_t*)(g_qf + off), EDIM,
        (const uint16_t*)(g_kf + off), EDIM,
        EDIM, 0.044194173824159216f, nullptr,
        nullptr, g_pf + z*(size_t)SEQ*SEQ, SEQ);
}
__global__ __launch_bounds__(256,2) void tc_attnout() {
    size_t z = blockIdx.z;
    size_t lh = z >> 1, b = z & 1;
    size_t l = lh / NH, h = lh % NH;
    size_t coff = l*(size_t)MROWS*CATH + b*(size_t)SEQ*CATH + h*EDIM;
    const int kBeg = blockIdx.y * 128;
    mma_gemm<3,false,false>((const uint16_t*)(g_pf + z*(size_t)SEQ*SEQ + kBeg), SEQ,
        (const uint16_t*)(g_vtf + z*(size_t)EDIM*SEQ + kBeg), SEQ,
        SEQ - kBeg, 1.f, nullptr, nullptr, g_ocf + coff, CATH);
}
__global__ __launch_bounds__(256,2) void tc_mh() {
    size_t l = blockIdx.z;
    mma_gemm<1,false,false>((const uint16_t*)(g_ocf + l*(size_t)MROWS*CATH), CATH,
        (const uint16_t*)(g_mwTf + l*(size_t)EDIM*CATH), CATH,
        CATH, 1.f, nullptr, g_t1 + l*(size_t)MROWS*EDIM, nullptr, EDIM);
}
__global__ __launch_bounds__(256,2) void tc_lin() {
    size_t l = blockIdx.z;
    mma_gemm<1,false,false>((const uint16_t*)(g_af + l*(size_t)MROWS*EDIM), EDIM,
        (const uint16_t*)(g_W123Tf + l*(size_t)EDIM*EDIM), EDIM,
        EDIM, 1.f, g_b123 + l*EDIM, g_t1 + l*(size_t)MROWS*EDIM, nullptr, EDIM);
}
// B = out_w f16 in ORIGINAL [CATL, VOCAB] layout, loaded via ldmatrix.trans
__global__ __launch_bounds__(256,2) void tc_final(const float* __restrict__ bias,
                                                  float* __restrict__ out) {
    mma_gemm<1,true,true>((const uint16_t*)g_catf, CATL,
        (const uint16_t*)g_owTf, VOCAB,
        CATL, 1.f, bias, out, nullptr, VOCAB);
}

// ---------------- fp32 SGEMM (for W123 precompute) ------------------------------
__device__ __forceinline__ float4 ld4(const float* p) {
    return *reinterpret_cast<const float4*>(p);
}
__device__ void sgemm_core(const float* __restrict__ A, int lda,
                           const float* __restrict__ B, int ldb,
                           float* __restrict__ C, int ldc, int K)
{
    __shared__ float As[8][128];
    __shared__ float Bs[8][128];
    const int tid = threadIdx.x;
    const int tx = tid & 15, ty = tid >> 4;
    const int lRow = tid >> 1, lCol = (tid & 1) << 2;
    const int bRow = tid >> 5, bCol = (tid & 31) << 2;
    const int bm = blockIdx.y, bn = blockIdx.x;
    const float* Ab = A + (size_t)bm * 128 * lda;
    const float* Bb = B + bn * 128;
    float acc[8][8];
    #pragma unroll
    for (int i = 0; i < 8; i++)
        #pragma unroll
        for (int j = 0; j < 8; j++) acc[i][j] = 0.f;
    for (int k0 = 0; k0 < K; k0 += 8) {
        float4 av = ld4(Ab + (size_t)lRow * lda + k0 + lCol);
        As[lCol+0][lRow] = av.x; As[lCol+1][lRow] = av.y;
        As[lCol+2][lRow] = av.z; As[lCol+3][lRow] = av.w;
        float4 bv = ld4(Bb + (size_t)(k0 + bRow) * ldb + bCol);
        *reinterpret_cast<float4*>(&Bs[bRow][bCol]) = bv;
        __syncthreads();
        #pragma unroll
        for (int kk = 0; kk < 8; kk++) {
            float4 a0 = ld4(&As[kk][ty*4]);
            float4 a1 = ld4(&As[kk][64 + ty*4]);
            float4 b0 = ld4(&Bs[kk][tx*4]);
            float4 b1 = ld4(&Bs[kk][64 + tx*4]);
            float ar[8] = {a0.x,a0.y,a0.z,a0.w, a1.x,a1.y,a1.z,a1.w};
            float br[8] = {b0.x,b0.y,b0.z,b0.w, b1.x,b1.y,b1.z,b1.w};
            #pragma unroll
            for (int i = 0; i < 8; i++)
                #pragma unroll
                for (int j = 0; j < 8; j++)
                    acc[i][j] = fmaf(ar[i], br[j], acc[i][j]);
        }
        __syncthreads();
    }
    #pragma unroll
    for (int i = 0; i < 8; i++) {
        int rloc = (i < 4) ? (ty*4 + i) : (64 + ty*4 + (i-4));
        size_t row = (size_t)bm * 128 + rloc;
        #pragma unroll
        for (int jh = 0; jh < 2; jh++) {
            int cloc = (jh == 0) ? (tx*4) : (64 + tx*4);
            int col = bn * 128 + cloc;
            float4 r;
            r.x = acc[i][jh*4+0]; r.y = acc[i][jh*4+1];
            r.z = acc[i][jh*4+2]; r.w = acc[i][jh*4+3];
            *reinterpret_cast<float4*>(&C[row * ldc + col]) = r;
        }
    }
}
__global__ __launch_bounds__(256) void k_w12(const float* __restrict__ w1,
                                             const float* __restrict__ w2) {
    size_t l = blockIdx.z;
    sgemm_core(w1 + l*EDIM*EDIM, EDIM, w2 + l*EDIM*EDIM, EDIM,
               g_w12 + l*EDIM*EDIM, EDIM, EDIM);
}
__global__ __launch_bounds__(256) void k_w123(const float* __restrict__ w3) {
    size_t l = blockIdx.z;
    sgemm_core(g_w12 + l*EDIM*EDIM, EDIM, w3 + l*EDIM*EDIM, EDIM,
               g_w123 + l*EDIM*EDIM, EDIM, EDIM);
}
__global__ void k_bfold1(const float* __restrict__ b1, const float* __restrict__ w2,
                         const float* __restrict__ b2) {
    int l = blockIdx.x, j = threadIdx.x;
    float s = b2[l*EDIM + j];
    const float* w = w2 + (size_t)l*EDIM*EDIM;
    const float* b = b1 + l*EDIM;
    for (int i = 0; i < EDIM; i++) s = fmaf(b[i], w[(size_t)i*EDIM + j], s);
    g_bt[l*EDIM + j] = s;
}
__global__ void k_bfold2(const float* __restrict__ w3, const float* __restrict__ b3) {
    int l = blockIdx.x, j = threadIdx.x;
    float s = b3[l*EDIM + j];
    const float* w = w3 + (size_t)l*EDIM*EDIM;
    const float* b = g_bt + l*EDIM;
    for (int i = 0; i < EDIM; i++) s = fmaf(b[i], w[(size_t)i*EDIM + j], s);
    g_b123[l*EDIM + j] = s;
}

// ---------------- small kernels --------------------------------------------------
__global__ void k_pvec() {
    int i = threadIdx.x;
    if (i < EDIM) {
        double denom = pow(10000.0, 2.0 * (double)i / (double)EDIM);
        double arg = (double)(SEQ - 1) / denom;
        g_pvec[i] = (i % 2 == 0) ? (float)sin(arg) : (float)cos(arg);
    }
}
__global__ void k_embed(const int* __restrict__ inputs, const float* __restrict__ emb) {
    int row = blockIdx.x;
    int idx = inputs[row];
    const float* src = emb + (size_t)idx * EDIM;
    for (int i = threadIdx.x; i < EDIM; i += blockDim.x) {
        float v = src[i] + g_pvec[i];
        g_x[(size_t)row * EDIM + i] = v;
        g_xf[(size_t)row * EDIM + i] = __float2half_rn(v);
    }
}
// streaming fp32 -> f16 convert (same layout); 8 elems/thread
__global__ __launch_bounds__(256) void k_conv(const float* __restrict__ in, int slot,
                                              size_t n) {
    f16* out = g_f16_tab[slot];
    size_t i = ((size_t)blockIdx.x * 256 + threadIdx.x) * 8;
    if (i >= n) return;
    float4 a = *reinterpret_cast<const float4*>(in + i);
    float4 b = *reinterpret_cast<const float4*>(in + i + 4);
    __half2 h0 = __floats2half2_rn(a.x, a.y);
    __half2 h1 = __floats2half2_rn(a.z, a.w);
    __half2 h2 = __floats2half2_rn(b.x, b.y);
    __half2 h3 = __floats2half2_rn(b.z, b.w);
    uint4 o;
    o.x = *reinterpret_cast<uint32_t*>(&h0);
    o.y = *reinterpret_cast<uint32_t*>(&h1);
    o.z = *reinterpret_cast<uint32_t*>(&h2);
    o.w = *reinterpret_cast<uint32_t*>(&h3);
    *reinterpret_cast<uint4*>(out + i) = o;
}
// warp-coalesced 64x64 transpose-convert: fp32 [R,C] (harness ptr) -> f16 [C,R]
__global__ __launch_bounds__(256) void k_tconvW(const float* __restrict__ in,
                                                int slot, int R, int C) {
    __shared__ float s[64][65];
    f16* out = g_f16_tab[slot];
    size_t zo = (size_t)blockIdx.z * ((size_t)R * C);
    int c0 = blockIdx.x * 64, r0 = blockIdx.y * 64;
    int tid = threadIdx.x;
    #pragma unroll
    for (int p = 0; p < 4; p++) {
        int idx = tid + p * 256;
        int r = idx >> 4, cs = (idx & 15) * 4;
        float4 v = *reinterpret_cast<const float4*>(in + zo + (size_t)(r0 + r) * C + c0 + cs);
        s[r][cs] = v.x; s[r][cs+1] = v.y; s[r][cs+2] = v.z; s[r][cs+3] = v.w;
    }
    __syncthreads();
    int w = tid >> 5, lane = tid & 31;
    #pragma unroll
    for (int i = 0; i < 8; i++) {
        int n = w * 8 + i;
        __half2 h = __floats2half2_rn(s[lane * 2][n], s[lane * 2 + 1][n]);
        *reinterpret_cast<__half2*>(out + zo + (size_t)(c0 + n) * R + r0 + lane * 2) = h;
    }
}
// g_vf -> g_vtf (R=SEQ, C=EDIM)
__global__ __launch_bounds__(256) void k_tconvW_v() {
    __shared__ float s[64][65];
    size_t zo = (size_t)blockIdx.z * SEQ * EDIM;
    int c0 = blockIdx.x * 64, r0 = blockIdx.y * 64;
    int tid = threadIdx.x;
    #pragma unroll
    for (int p = 0; p < 4; p++) {
        int idx = tid + p * 256;
        int r = idx >> 4, cs = (idx & 15) * 4;
        float4 v = *reinterpret_cast<const float4*>(g_vf + zo + (size_t)(r0 + r) * EDIM + c0 + cs);
        s[r][cs] = v.x; s[r][cs+1] = v.y; s[r][cs+2] = v.z; s[r][cs+3] = v.w;
    }
    __syncthreads();
    int w = tid >> 5, lane = tid & 31;
    #pragma unroll
    for (int i = 0; i < 8; i++) {
        int n = w * 8 + i;
        __half2 h = __floats2half2_rn(s[lane * 2][n], s[lane * 2 + 1][n]);
        *reinterpret_cast<__half2*>(g_vtf + zo + (size_t)(c0 + n) * SEQ + r0 + lane * 2) = h;
    }
}
// g_w123 -> g_W123Tf
__global__ __launch_bounds__(256) void k_tconvW_123() {
    __shared__ float s[64][65];
    size_t zo = (size_t)blockIdx.z * EDIM * EDIM;
    int c0 = blockIdx.x * 64, r0 = blockIdx.y * 64;
    int tid = threadIdx.x;
    #pragma unroll
    for (int p = 0; p < 4; p++) {
        int idx = tid + p * 256;
        int r = idx >> 4, cs = (idx & 15) * 4;
        float4 v = *reinterpret_cast<const float4*>(g_w123 + zo + (size_t)(r0 + r) * EDIM + c0 + cs);
        s[r][cs] = v.x; s[r][cs+1] = v.y; s[r][cs+2] = v.z; s[r][cs+3] = v.w;
    }
    __syncthreads();
    int w = tid >> 5, lane = tid & 31;
    #pragma unroll
    for (int i = 0; i < 8; i++) {
        int n = w * 8 + i;
        __half2 h = __floats2half2_rn(s[lane * 2][n], s[lane * 2 + 1][n]);
        *reinterpret_cast<__half2*>(g_W123Tf + zo + (size_t)(c0 + n) * EDIM + r0 + lane * 2) = h;
    }
}
// column softmax over query axis s (masked s<=t) on f16 exp values, in place
__global__ void k_softmax() {
    size_t z = blockIdx.y;
    int t0 = (blockIdx.x * blockDim.x + threadIdx.x) * 2;
    f16* pf = g_pf + z * (size_t)SEQ * SEQ;
    float s0 = 0.f, s1 = 0.f;
    for (int s = 0; s <= t0 + 1; s++) {
        __half2 e = *reinterpret_cast<__half2*>(pf + (size_t)s * SEQ + t0);
        float2 ef = __half22float2(e);
        if (s <= t0) s0 += ef.x;
        s1 += ef.y;
    }
    float i0 = 1.f / s0, i1 = 1.f / s1;
    for (int s = 0; s < SEQ; s++) {
        __half2 e = *reinterpret_cast<__half2*>(pf + (size_t)s * SEQ + t0);
        float2 ef = __half22float2(e);
        float p0 = (s <= t0)     ? ef.x * i0 : 0.f;
        float p1 = (s <= t0 + 1) ? ef.y * i1 : 0.f;
        *reinterpret_cast<__half2*>(pf + (size_t)s * SEQ + t0) = __floats2half2_rn(p0, p1);
    }
}
__device__ __forceinline__ float block_reduce128(float v) {
    __shared__ float sh[4];
    #pragma unroll
    for (int o = 16; o > 0; o >>= 1) v += __shfl_down_sync(0xffffffffu, v, o);
    int lane = threadIdx.x & 31, w = threadIdx.x >> 5;
    if (lane == 0) sh[w] = v;
    __syncthreads();
    float r = sh[0] + sh[1] + sh[2] + sh[3];
    __syncthreads();
    return r;
}
__global__ void k_ln_a(const float* __restrict__ mh_b, const float* __restrict__ ln_g,
                       const float* __restrict__ ln_b) {
    int l = blockIdx.y;
    size_t row = blockIdx.x;
    const float* xr = g_x + row * EDIM;
    const float* tr = g_t1 + ((size_t)l * MROWS + row) * EDIM;
    const float* mb = mh_b + (size_t)l * EDIM;
    int base = threadIdx.x * 4;
    float v[4]; float s = 0.f;
    #pragma unroll
    for (int j = 0; j < 4; j++) { v[j] = xr[base+j] + tr[base+j] + mb[base+j]; s += v[j]; }
    float mean = block_reduce128(s) * (1.f / EDIM);
    float s2 = 0.f;
    #pragma unroll
    for (int j = 0; j < 4; j++) { float d = v[j] - mean; s2 += d * d; }
    float var = block_reduce128(s2) * (1.f / EDIM);
    float inv = rsqrtf(var + 1e-5f);
    const float* g = ln_g + (size_t)l * EDIM;
    const float* b = ln_b + (size_t)l * EDIM;
    size_t o = ((size_t)l * MROWS + row) * EDIM + base;
    #pragma unroll
    for (int j = 0; j < 4; j++) {
        float r = (v[j] - mean) * inv * g[base+j] + b[base+j];
        g_a[o+j] = r;
        g_af[o+j] = __float2half_rn(r);
    }
}
__global__ void k_ln_cat(const float* __restrict__ ln_g, const float* __restrict__ ln_b) {
    int l = blockIdx.y;
    size_t row = blockIdx.x;
    const float* tr = g_t1 + ((size_t)l * MROWS + row) * EDIM;
    const float* ar = g_a + ((size_t)l * MROWS + row) * EDIM;
    int base = threadIdx.x * 4;
    float v[4]; float s = 0.f;
    #pragma unroll
    for (int j = 0; j < 4; j++) { v[j] = tr[base+j] + ar[base+j]; s += v[j]; }
    float mean = block_reduce128(s) * (1.f / EDIM);
    float s2 = 0.f;
    #pragma unroll
    for (int j = 0; j < 4; j++) { float d = v[j] - mean; s2 += d * d; }
    float var = block_reduce128(s2) * (1.f / EDIM);
    float inv = rsqrtf(var + 1e-5f);
    const float* g = ln_g + (size_t)l * EDIM;
    const float* b = ln_b + (size_t)l * EDIM;
    size_t o = row * CATL + (size_t)l * EDIM + base;
    #pragma unroll
    for (int j = 0; j < 4; j++) {
        float r = (v[j] - mean) * inv * g[base+j] + b[base+j];
        g_catf[o+j] = __float2half_rn(r);
    }
}

// ---------------- launch ----------------------------------------------------------
extern "C" void kernel_launch(void* const* d_in, const int* in_sizes, int n_in,
                              void* d_out, int out_size) {
    (void)n_in; (void)out_size;
    const int*   inputs = (const int*)d_in[0];
    const float* emb_w  = (const float*)d_in[1];
    const float* Wq     = (const float*)d_in[2];
    const float* Wk     = (const float*)d_in[3];
    const float* Wv     = (const float*)d_in[4];
    const float *mh_w, *mh_b;
    if (in_sizes[5] == NL * EDIM) { mh_b = (const float*)d_in[5]; mh_w = (const float*)d_in[6]; }
    else                          { mh_w = (const float*)d_in[5]; mh_b = (const float*)d_in[6]; }
    const float* l1_w = (const float*)d_in[7];
    const float* l1_b = (const float*)d_in[8];
    const float* l2_w = (const float*)d_in[9];
    const float* l2_b = (const float*)d_in[10];
    const float* l3_w = (const float*)d_in[11];
    const float* l3_b = (const float*)d_in[12];
    const float* ln_g = (const float*)d_in[13];
    const float* ln_b = (const float*)d_in[14];
    const float* out_w = (const float*)d_in[15];
    const float* out_b = (const float*)d_in[16];
    float* out = (float*)d_out;

    k_pvec<<<1, 512>>>();
    k_embed<<<MROWS, 128>>>(inputs, emb_w);
    k_tconvW<<<dim3(EDIM/64, EDIM/64, LHN), 256>>>(Wq, 0, EDIM, EDIM);
    k_tconvW<<<dim3(EDIM/64, EDIM/64, LHN), 256>>>(Wk, 1, EDIM, EDIM);
    k_tconvW<<<dim3(EDIM/64, EDIM/64, LHN), 256>>>(Wv, 2, EDIM, EDIM);
    tc_qkv<<<dim3(EDIM/128, MROWS/128, 3*LHN), 256>>>();
    k_tconvW_v<<<dim3(EDIM/64, SEQ/64, LHN*BATCH), 256>>>();
    tc_score<<<dim3(SEQ/128, SEQ/128, LHN*BATCH), 256>>>();
    k_softmax<<<dim3(SEQ/256, LHN*BATCH), 128>>>();
    tc_attnout<<<dim3(EDIM/128, SEQ/128, LHN*BATCH), 256>>>();
    k_tconvW<<<dim3(EDIM/64, CATH/64, NL), 256>>>(mh_w, 4, CATH, EDIM);
    tc_mh<<<dim3(EDIM/128, MROWS/128, NL), 256>>>();
    k_ln_a<<<dim3(MROWS, NL), 128>>>(mh_b, ln_g, ln_b);
    k_w12<<<dim3(4,4,NL), 256>>>(l1_w, l2_w);
    k_w123<<<dim3(4,4,NL), 256>>>(l3_w);
    k_bfold1<<<NL, EDIM>>>(l1_b, l2_w, l2_b);
    k_bfold2<<<NL, EDIM>>>(l3_w, l3_b);
    k_tconvW_123<<<dim3(EDIM/64, EDIM/64, NL), 256>>>();
    tc_lin<<<dim3(EDIM/128, MROWS/128, NL), 256>>>();
    k_ln_cat<<<dim3(MROWS, NL), 128>>>(ln_g, ln_b);
    // out_w: streaming convert, SAME layout [CATL, VOCAB]
    k_conv<<<(int)(((size_t)CATL*VOCAB/8 + 255)/256), 256>>>(out_w, 3, (size_t)CATL*VOCAB);
    tc_final<<<dim3(MROWS/128, VOCAB/128, 1), 256>>>(out_b, out);
}

// round 16
// speedup vs baseline: 1.1091x; 1.0211x over previous
#include <cuda_runtime.h>
#include <cuda_bf16.h>
#include <cuda_fp16.h>
#include <math.h>
#include <stdint.h>

#define EDIM  512
#define SEQ   1024
#define BATCH 2
#define NL    6
#define NH    3
#define VOCAB 32000
#define MROWS (BATCH*SEQ)
#define CATH  (NH*EDIM)
#define CATL  (NL*EDIM)
#define LHN   (NL*NH)

using bf16 = __nv_bfloat16;
using f16  = __half;

// ---------------- scratch ----------------------------------------------------
static __device__ float g_pvec[EDIM];
static __device__ float g_x   [MROWS*EDIM];
static __device__ f16   g_xf  [MROWS*EDIM];
static __device__ f16   g_WqTf[(size_t)LHN*EDIM*EDIM];
static __device__ f16   g_WkTf[(size_t)LHN*EDIM*EDIM];
static __device__ f16   g_WvTf[(size_t)LHN*EDIM*EDIM];
static __device__ f16   g_owTf[(size_t)VOCAB*CATL];   // [CATL, VOCAB] k-major (BT path)
static __device__ f16   g_mwTf[(size_t)NL*EDIM*CATH];
static __device__ f16   g_qf  [(size_t)LHN*MROWS*EDIM];
static __device__ f16   g_kf  [(size_t)LHN*MROWS*EDIM];
static __device__ float g_vf  [(size_t)LHN*MROWS*EDIM];
static __device__ f16   g_vtf [(size_t)LHN*MROWS*EDIM];
static __device__ f16   g_pf  [(size_t)LHN*BATCH*SEQ*SEQ];  // masked exp(score)
static __device__ float g_sinv[(size_t)LHN*BATCH*SEQ];       // 1 / column sums
static __device__ f16   g_ocf [(size_t)NL*MROWS*CATH];
static __device__ float g_t1  [(size_t)NL*MROWS*EDIM];
static __device__ float g_a   [(size_t)NL*MROWS*EDIM];
static __device__ f16   g_af  [(size_t)NL*MROWS*EDIM];
static __device__ f16   g_catf[(size_t)MROWS*CATL];
static __device__ float g_w12 [(size_t)NL*EDIM*EDIM];
static __device__ float g_w123[(size_t)NL*EDIM*EDIM];
static __device__ f16   g_W123Tf[(size_t)NL*EDIM*EDIM];
static __device__ float g_bt  [NL*EDIM];
static __device__ float g_b123[NL*EDIM];

static __device__ f16* const g_f16_tab[5] = { g_WqTf, g_WkTf, g_WvTf, g_owTf, g_mwTf };

// ---------------- helpers -----------------------------------------------------
__device__ __forceinline__ uint32_t cvsm(const void* p) {
    return (uint32_t)__cvta_generic_to_shared(p);
}
__device__ __forceinline__ void cpa16(uint32_t saddr, const void* g) {
    asm volatile("cp.async.cg.shared.global [%0], [%1], 16;" :: "r"(saddr), "l"(g));
}
__device__ __forceinline__ void ldm4(uint32_t* r, uint32_t addr) {
    asm volatile("ldmatrix.sync.aligned.m8n8.x4.shared.b16 {%0,%1,%2,%3}, [%4];"
        : "=r"(r[0]), "=r"(r[1]), "=r"(r[2]), "=r"(r[3]) : "r"(addr));
}
__device__ __forceinline__ void ldm4t(uint32_t* r, uint32_t addr) {
    asm volatile("ldmatrix.sync.aligned.m8n8.x4.trans.shared.b16 {%0,%1,%2,%3}, [%4];"
        : "=r"(r[0]), "=r"(r[1]), "=r"(r[2]), "=r"(r[3]) : "r"(addr));
}
__device__ __forceinline__ void mma_h(float* d, const uint32_t* a, uint32_t b0, uint32_t b1) {
    asm volatile("mma.sync.aligned.m16n8k16.row.col.f32.f16.f16.f32 "
        "{%0,%1,%2,%3}, {%4,%5,%6,%7}, {%8,%9}, {%0,%1,%2,%3};"
        : "+f"(d[0]), "+f"(d[1]), "+f"(d[2]), "+f"(d[3])
        : "r"(a[0]), "r"(a[1]), "r"(a[2]), "r"(a[3]), "r"(b0), "r"(b1));
}

// ---------------- fp16 single-product GEMM: C = alpha*A@B^T (+bias) ------------
// EPI 1: fp32. EPI 3: f16. EPI 4: f16 masked exp: (row<=col ? exp(v) : 0).
// BT=false: B stored [N,K] row-major. BT=true: B stored [K,N], ldmatrix.trans.
// Tile 128x128, BK=16, 8 warps (2M x 4N). 3-stage pipeline, single barrier:
// wait -> sync -> compute -> issue loads for c+2.
template<int EPI, bool SWAP, bool BT>
__device__ __forceinline__ void mma_gemm(
    const uint16_t* __restrict__ Ah, int lda,
    const uint16_t* __restrict__ Bh, int ldb,
    int K, float alpha, const float* __restrict__ bias,
    float* __restrict__ Cf, void* __restrict__ C1, int ldc)
{
    constexpr int TILE = 4096;
    constexpr int STB  = 2*TILE;
    __shared__ __align__(128) char smem[3 * STB];
    const uint32_t sm0 = cvsm(smem);
    const int tid = threadIdx.x, lane = tid & 31, wid = tid >> 5;
    const int wm = wid & 1, wn = wid >> 1;
    const int bm = SWAP ? blockIdx.x : blockIdx.y;
    const int bn = SWAP ? blockIdx.y : blockIdx.x;
    const int mBase = bm * 128, nBase = bn * 128;

    const int crow = tid >> 1, cseg = tid & 1;
    const uint32_t cdstA = (uint32_t)(crow * 32 + ((cseg ^ ((crow >> 2) & 1)) << 4));
    const uint16_t* gA0 = Ah + (size_t)(mBase + crow) * lda + cseg * 8;

    uint32_t cdstB;
    const uint16_t* gB0;
    if (BT) {
        const int krow = tid >> 4, seg = tid & 15;
        cdstB = (uint32_t)(krow * 256 + ((seg ^ (krow & 7)) << 4));
        gB0 = Bh + (size_t)krow * ldb + nBase + seg * 8;
    } else {
        cdstB = cdstA;
        gB0 = Bh + (size_t)(nBase + crow) * ldb + cseg * 8;
    }

    const int lrow = lane & 15, kseg = lane >> 4;
    uint32_t offA[4], offB[2];
    #pragma unroll
    for (int mf = 0; mf < 4; ++mf) {
        int r = wm * 64 + mf * 16 + lrow;
        offA[mf] = (uint32_t)(r * 32 + ((kseg ^ ((r >> 2) & 1)) << 4));
    }
    if (BT) {
        const int kk = (lane & 7) | ((lane & 16) >> 1);
        const int nb = (lane >> 3) & 1;
        #pragma unroll
        for (int j = 0; j < 2; ++j) {
            int gb = wn * 4 + j * 2 + nb;
            offB[j] = (uint32_t)(kk * 256 + ((gb ^ (kk & 7)) << 4));
        }
    } else {
        #pragma unroll
        for (int j = 0; j < 2; ++j) {
            int r = wn * 32 + j * 16 + lrow;
            offB[j] = (uint32_t)(r * 32 + ((kseg ^ ((r >> 2) & 1)) << 4));
        }
    }

    float acc[4][4][4];
    #pragma unroll
    for (int i = 0; i < 4; ++i)
        #pragma unroll
        for (int j = 0; j < 4; ++j)
            #pragma unroll
            for (int q = 0; q < 4; ++q) acc[i][j][q] = 0.f;

    const int nCh = K >> 4;
    #pragma unroll
    for (int p = 0; p < 2; ++p) {
        if (p < nCh) {
            const uint32_t sb = sm0 + (uint32_t)p * STB;
            const int ke = p << 4;
            cpa16(sb + cdstA, gA0 + ke);
            cpa16(sb + TILE + cdstB, gB0 + (BT ? (size_t)ke * ldb : (size_t)ke));
            asm volatile("cp.async.commit_group;");
        }
    }

    int stage = 0, lstage = 2;
    for (int c = 0; c < nCh; ++c) {
        if (c + 1 < nCh) asm volatile("cp.async.wait_group 1;");
        else             asm volatile("cp.async.wait_group 0;");
        __syncthreads();

        const uint32_t sb = sm0 + (uint32_t)stage * STB;
        uint32_t ah[4][4], bh[2][4];
        #pragma unroll
        for (int mf = 0; mf < 4; ++mf) ldm4(ah[mf], sb + offA[mf]);
        #pragma unroll
        for (int j = 0; j < 2; ++j) {
            if (BT) ldm4t(bh[j], sb + TILE + offB[j]);
            else    ldm4 (bh[j], sb + TILE + offB[j]);
        }
        #pragma unroll
        for (int mf = 0; mf < 4; ++mf) {
            #pragma unroll
            for (int j = 0; j < 2; ++j) {
                mma_h(acc[mf][2*j],   ah[mf], bh[j][0], bh[j][2]);
                mma_h(acc[mf][2*j+1], ah[mf], bh[j][1], bh[j][3]);
            }
        }

        if (c + 2 < nCh) {
            const uint32_t sb2 = sm0 + (uint32_t)lstage * STB;
            const int ke = (c + 2) << 4;
            cpa16(sb2 + cdstA, gA0 + ke);
            cpa16(sb2 + TILE + cdstB, gB0 + (BT ? (size_t)ke * ldb : (size_t)ke));
            asm volatile("cp.async.commit_group;");
        }
        if (++stage == 3) stage = 0;
        if (++lstage == 3) lstage = 0;
    }

    const int g = lane >> 2, t = lane & 3;
    #pragma unroll
    for (int nb = 0; nb < 4; ++nb) {
        const int col = nBase + wn * 32 + nb * 8 + t * 2;
        float b0 = 0.f, b1 = 0.f;
        if (bias) { b0 = bias[col]; b1 = bias[col + 1]; }
        #pragma unroll
        for (int mf = 0; mf < 4; ++mf) {
            const int row0 = mBase + wm * 64 + mf * 16 + g;
            float v0 = fmaf(alpha, acc[mf][nb][0], b0);
            float v1 = fmaf(alpha, acc[mf][nb][1], b1);
            float v2 = fmaf(alpha, acc[mf][nb][2], b0);
            float v3 = fmaf(alpha, acc[mf][nb][3], b1);
            const size_t gidx  = (size_t)row0 * ldc + col;
            const size_t gidx2 = (size_t)(row0 + 8) * ldc + col;
            if (EPI == 1) {
                float2 p0; p0.x = v0; p0.y = v1;
                float2 p1; p1.x = v2; p1.y = v3;
                *reinterpret_cast<float2*>(Cf + gidx)  = p0;
                *reinterpret_cast<float2*>(Cf + gidx2) = p1;
            } else if (EPI == 3) {
                f16* Chf = (f16*)C1;
                __half2 p0 = __floats2half2_rn(v0, v1);
                __half2 p1 = __floats2half2_rn(v2, v3);
                *reinterpret_cast<__half2*>(Chf + gidx)  = p0;
                *reinterpret_cast<__half2*>(Chf + gidx2) = p1;
            } else {
                // EPI 4: masked exp (s<=t), s = row, t = col
                f16* Chf = (f16*)C1;
                float e0 = (row0     <= col)     ? __expf(v0) : 0.f;
                float e1 = (row0     <= col + 1) ? __expf(v1) : 0.f;
                float e2 = (row0 + 8 <= col)     ? __expf(v2) : 0.f;
                float e3 = (row0 + 8 <= col + 1) ? __expf(v3) : 0.f;
                __half2 p0 = __floats2half2_rn(e0, e1);
                __half2 p1 = __floats2half2_rn(e2, e3);
                *reinterpret_cast<__half2*>(Chf + gidx)  = p0;
                *reinterpret_cast<__half2*>(Chf + gidx2) = p1;
            }
        }
    }
}

// ---------------- GEMM wrapper kernels -----------------------------------------
__global__ __launch_bounds__(256,2) void tc_qkv() {
    int z = blockIdx.z;
    int which = z / LHN;
    size_t lh = z % LHN;
    const uint16_t* A = (const uint16_t*)g_xf;
    if (which == 0) {
        mma_gemm<3,false,false>(A, EDIM, (const uint16_t*)(g_WqTf + lh*EDIM*EDIM), EDIM,
            EDIM, 1.f, nullptr, nullptr, g_qf + lh*(size_t)MROWS*EDIM, EDIM);
    } else if (which == 1) {
        mma_gemm<3,false,false>(A, EDIM, (const uint16_t*)(g_WkTf + lh*EDIM*EDIM), EDIM,
            EDIM, 1.f, nullptr, nullptr, g_kf + lh*(size_t)MROWS*EDIM, EDIM);
    } else {
        mma_gemm<1,false,false>(A, EDIM, (const uint16_t*)(g_WvTf + lh*EDIM*EDIM), EDIM,
            EDIM, 1.f, nullptr, g_vf + lh*(size_t)MROWS*EDIM, nullptr, EDIM);
    }
}
__global__ __launch_bounds__(256,2) void tc_score() {
    if (blockIdx.y > blockIdx.x) return;
    size_t z = blockIdx.z;
    size_t off = z * (size_t)SEQ * EDIM;
    mma_gemm<4,false,false>((const uint16_t*)(g_qf + off), EDIM,
        (const uint16_t*)(g_kf + off), EDIM,
        EDIM, 0.044194173824159216f, nullptr,
        nullptr, g_pf + z*(size_t)SEQ*SEQ, SEQ);
}
__global__ __launch_bounds__(256,2) void tc_attnout() {
    size_t z = blockIdx.z;
    size_t lh = z >> 1, b = z & 1;
    size_t l = lh / NH, h = lh % NH;
    size_t coff = l*(size_t)MROWS*CATH + b*(size_t)SEQ*CATH + h*EDIM;
    const int kBeg = blockIdx.y * 128;
    mma_gemm<3,false,false>((const uint16_t*)(g_pf + z*(size_t)SEQ*SEQ + kBeg), SEQ,
        (const uint16_t*)(g_vtf + z*(size_t)EDIM*SEQ + kBeg), SEQ,
        SEQ - kBeg, 1.f, nullptr, nullptr, g_ocf + coff, CATH);
}
__global__ __launch_bounds__(256,2) void tc_mh() {
    size_t l = blockIdx.z;
    mma_gemm<1,false,false>((const uint16_t*)(g_ocf + l*(size_t)MROWS*CATH), CATH,
        (const uint16_t*)(g_mwTf + l*(size_t)EDIM*CATH), CATH,
        CATH, 1.f, nullptr, g_t1 + l*(size_t)MROWS*EDIM, nullptr, EDIM);
}
__global__ __launch_bounds__(256,2) void tc_lin() {
    size_t l = blockIdx.z;
    mma_gemm<1,false,false>((const uint16_t*)(g_af + l*(size_t)MROWS*EDIM), EDIM,
        (const uint16_t*)(g_W123Tf + l*(size_t)EDIM*EDIM), EDIM,
        EDIM, 1.f, g_b123 + l*EDIM, g_t1 + l*(size_t)MROWS*EDIM, nullptr, EDIM);
}
__global__ __launch_bounds__(256,2) void tc_final(const float* __restrict__ bias,
                                                  float* __restrict__ out) {
    mma_gemm<1,true,true>((const uint16_t*)g_catf, CATL,
        (const uint16_t*)g_owTf, VOCAB,
        CATL, 1.f, bias, out, nullptr, VOCAB);
}

// ---------------- fp32 SGEMM (for W123 precompute) ------------------------------
__device__ __forceinline__ float4 ld4(const float* p) {
    return *reinterpret_cast<const float4*>(p);
}
__device__ void sgemm_core(const float* __restrict__ A, int lda,
                           const float* __restrict__ B, int ldb,
                           float* __restrict__ C, int ldc, int K)
{
    __shared__ float As[8][128];
    __shared__ float Bs[8][128];
    const int tid = threadIdx.x;
    const int tx = tid & 15, ty = tid >> 4;
    const int lRow = tid >> 1, lCol = (tid & 1) << 2;
    const int bRow = tid >> 5, bCol = (tid & 31) << 2;
    const int bm = blockIdx.y, bn = blockIdx.x;
    const float* Ab = A + (size_t)bm * 128 * lda;
    const float* Bb = B + bn * 128;
    float acc[8][8];
    #pragma unroll
    for (int i = 0; i < 8; i++)
        #pragma unroll
        for (int j = 0; j < 8; j++) acc[i][j] = 0.f;
    for (int k0 = 0; k0 < K; k0 += 8) {
        float4 av = ld4(Ab + (size_t)lRow * lda + k0 + lCol);
        As[lCol+0][lRow] = av.x; As[lCol+1][lRow] = av.y;
        As[lCol+2][lRow] = av.z; As[lCol+3][lRow] = av.w;
        float4 bv = ld4(Bb + (size_t)(k0 + bRow) * ldb + bCol);
        *reinterpret_cast<float4*>(&Bs[bRow][bCol]) = bv;
        __syncthreads();
        #pragma unroll
        for (int kk = 0; kk < 8; kk++) {
            float4 a0 = ld4(&As[kk][ty*4]);
            float4 a1 = ld4(&As[kk][64 + ty*4]);
            float4 b0 = ld4(&Bs[kk][tx*4]);
            float4 b1 = ld4(&Bs[kk][64 + tx*4]);
            float ar[8] = {a0.x,a0.y,a0.z,a0.w, a1.x,a1.y,a1.z,a1.w};
            float br[8] = {b0.x,b0.y,b0.z,b0.w, b1.x,b1.y,b1.z,b1.w};
            #pragma unroll
            for (int i = 0; i < 8; i++)
                #pragma unroll
                for (int j = 0; j < 8; j++)
                    acc[i][j] = fmaf(ar[i], br[j], acc[i][j]);
        }
        __syncthreads();
    }
    #pragma unroll
    for (int i = 0; i < 8; i++) {
        int rloc = (i < 4) ? (ty*4 + i) : (64 + ty*4 + (i-4));
        size_t row = (size_t)bm * 128 + rloc;
        #pragma unroll
        for (int jh = 0; jh < 2; jh++) {
            int cloc = (jh == 0) ? (tx*4) : (64 + tx*4);
            int col = bn * 128 + cloc;
            float4 r;
            r.x = acc[i][jh*4+0]; r.y = acc[i][jh*4+1];
            r.z = acc[i][jh*4+2]; r.w = acc[i][jh*4+3];
            *reinterpret_cast<float4*>(&C[row * ldc + col]) = r;
        }
    }
}
__global__ __launch_bounds__(256) void k_w12(const float* __restrict__ w1,
                                             const float* __restrict__ w2) {
    size_t l = blockIdx.z;
    sgemm_core(w1 + l*EDIM*EDIM, EDIM, w2 + l*EDIM*EDIM, EDIM,
               g_w12 + l*EDIM*EDIM, EDIM, EDIM);
}
__global__ __launch_bounds__(256) void k_w123(const float* __restrict__ w3) {
    size_t l = blockIdx.z;
    sgemm_core(g_w12 + l*EDIM*EDIM, EDIM, w3 + l*EDIM*EDIM, EDIM,
               g_w123 + l*EDIM*EDIM, EDIM, EDIM);
}
__global__ void k_bfold1(const float* __restrict__ b1, const float* __restrict__ w2,
                         const float* __restrict__ b2) {
    int l = blockIdx.x, j = threadIdx.x;
    float s = b2[l*EDIM + j];
    const float* w = w2 + (size_t)l*EDIM*EDIM;
    const float* b = b1 + l*EDIM;
    for (int i = 0; i < EDIM; i++) s = fmaf(b[i], w[(size_t)i*EDIM + j], s);
    g_bt[l*EDIM + j] = s;
}
__global__ void k_bfold2(const float* __restrict__ w3, const float* __restrict__ b3) {
    int l = blockIdx.x, j = threadIdx.x;
    float s = b3[l*EDIM + j];
    const float* w = w3 + (size_t)l*EDIM*EDIM;
    const float* b = g_bt + l*EDIM;
    for (int i = 0; i < EDIM; i++) s = fmaf(b[i], w[(size_t)i*EDIM + j], s);
    g_b123[l*EDIM + j] = s;
}

// ---------------- small kernels --------------------------------------------------
__global__ void k_pvec() {
    int i = threadIdx.x;
    if (i < EDIM) {
        double denom = pow(10000.0, 2.0 * (double)i / (double)EDIM);
        double arg = (double)(SEQ - 1) / denom;
        g_pvec[i] = (i % 2 == 0) ? (float)sin(arg) : (float)cos(arg);
    }
}
__global__ void k_embed(const int* __restrict__ inputs, const float* __restrict__ emb) {
    int row = blockIdx.x;
    int idx = inputs[row];
    const float* src = emb + (size_t)idx * EDIM;
    for (int i = threadIdx.x; i < EDIM; i += blockDim.x) {
        float v = src[i] + g_pvec[i];
        g_x[(size_t)row * EDIM + i] = v;
        g_xf[(size_t)row * EDIM + i] = __float2half_rn(v);
    }
}
// streaming fp32 -> f16 convert (same layout); 8 elems/thread
__global__ __launch_bounds__(256) void k_conv(const float* __restrict__ in, int slot,
                                              size_t n) {
    f16* out = g_f16_tab[slot];
    size_t i = ((size_t)blockIdx.x * 256 + threadIdx.x) * 8;
    if (i >= n) return;
    float4 a = *reinterpret_cast<const float4*>(in + i);
    float4 b = *reinterpret_cast<const float4*>(in + i + 4);
    __half2 h0 = __floats2half2_rn(a.x, a.y);
    __half2 h1 = __floats2half2_rn(a.z, a.w);
    __half2 h2 = __floats2half2_rn(b.x, b.y);
    __half2 h3 = __floats2half2_rn(b.z, b.w);
    uint4 o;
    o.x = *reinterpret_cast<uint32_t*>(&h0);
    o.y = *reinterpret_cast<uint32_t*>(&h1);
    o.z = *reinterpret_cast<uint32_t*>(&h2);
    o.w = *reinterpret_cast<uint32_t*>(&h3);
    *reinterpret_cast<uint4*>(out + i) = o;
}
// warp-coalesced 64x64 transpose-convert: fp32 [R,C] (harness ptr) -> f16 [C,R]
__global__ __launch_bounds__(256) void k_tconvW(const float* __restrict__ in,
                                                int slot, int R, int C) {
    __shared__ float s[64][65];
    f16* out = g_f16_tab[slot];
    size_t zo = (size_t)blockIdx.z * ((size_t)R * C);
    int c0 = blockIdx.x * 64, r0 = blockIdx.y * 64;
    int tid = threadIdx.x;
    #pragma unroll
    for (int p = 0; p < 4; p++) {
        int idx = tid + p * 256;
        int r = idx >> 4, cs = (idx & 15) * 4;
        float4 v = *reinterpret_cast<const float4*>(in + zo + (size_t)(r0 + r) * C + c0 + cs);
        s[r][cs] = v.x; s[r][cs+1] = v.y; s[r][cs+2] = v.z; s[r][cs+3] = v.w;
    }
    __syncthreads();
    int w = tid >> 5, lane = tid & 31;
    #pragma unroll
    for (int i = 0; i < 8; i++) {
        int n = w * 8 + i;
        __half2 h = __floats2half2_rn(s[lane * 2][n], s[lane * 2 + 1][n]);
        *reinterpret_cast<__half2*>(out + zo + (size_t)(c0 + n) * R + r0 + lane * 2) = h;
    }
}
// g_vf -> g_vtf with per-t 1/S scale: v'[f][t] = v[t][f] * sinv[z][t]
__global__ __launch_bounds__(256) void k_tconvW_vs() {
    __shared__ float s[64][65];
    size_t z = blockIdx.z;
    size_t zo = z * (size_t)SEQ * EDIM;
    int c0 = blockIdx.x * 64, r0 = blockIdx.y * 64;
    int tid = threadIdx.x;
    #pragma unroll
    for (int p = 0; p < 4; p++) {
        int idx = tid + p * 256;
        int r = idx >> 4, cs = (idx & 15) * 4;
        float4 v = *reinterpret_cast<const float4*>(g_vf + zo + (size_t)(r0 + r) * EDIM + c0 + cs);
        s[r][cs] = v.x; s[r][cs+1] = v.y; s[r][cs+2] = v.z; s[r][cs+3] = v.w;
    }
    __syncthreads();
    int w = tid >> 5, lane = tid & 31;
    const float i0 = g_sinv[z * SEQ + r0 + lane * 2];
    const float i1 = g_sinv[z * SEQ + r0 + lane * 2 + 1];
    #pragma unroll
    for (int i = 0; i < 8; i++) {
        int n = w * 8 + i;
        __half2 h = __floats2half2_rn(s[lane * 2][n] * i0, s[lane * 2 + 1][n] * i1);
        *reinterpret_cast<__half2*>(g_vtf + zo + (size_t)(c0 + n) * SEQ + r0 + lane * 2) = h;
    }
}
// g_w123 -> g_W123Tf
__global__ __launch_bounds__(256) void k_tconvW_123() {
    __shared__ float s[64][65];
    size_t zo = (size_t)blockIdx.z * EDIM * EDIM;
    int c0 = blockIdx.x * 64, r0 = blockIdx.y * 64;
    int tid = threadIdx.x;
    #pragma unroll
    for (int p = 0; p < 4; p++) {
        int idx = tid + p * 256;
        int r = idx >> 4, cs = (idx & 15) * 4;
        float4 v = *reinterpret_cast<const float4*>(g_w123 + zo + (size_t)(r0 + r) * EDIM + c0 + cs);
        s[r][cs] = v.x; s[r][cs+1] = v.y; s[r][cs+2] = v.z; s[r][cs+3] = v.w;
    }
    __syncthreads();
    int w = tid >> 5, lane = tid & 31;
    #pragma unroll
    for (int i = 0; i < 8; i++) {
        int n = w * 8 + i;
        __half2 h = __floats2half2_rn(s[lane * 2][n], s[lane * 2 + 1][n]);
        *reinterpret_cast<__half2*>(g_W123Tf + zo + (size_t)(c0 + n) * EDIM + r0 + lane * 2) = h;
    }
}
// column sums of masked exp: g_sinv[z][t] = 1 / sum_{s<=t} E[s][t]
__global__ void k_colsum() {
    size_t z = blockIdx.y;
    int t = blockIdx.x * 256 + threadIdx.x;
    const f16* pf = g_pf + z * (size_t)SEQ * SEQ;
    float s = 0.f;
    for (int r = 0; r <= t; r++) s += __half2float(pf[(size_t)r * SEQ + t]);
    g_sinv[z * SEQ + t] = 1.f / s;
}
__device__ __forceinline__ float block_reduce128(float v) {
    __shared__ float sh[4];
    #pragma unroll
    for (int o = 16; o > 0; o >>= 1) v += __shfl_down_sync(0xffffffffu, v, o);
    int lane = threadIdx.x & 31, w = threadIdx.x >> 5;
    if (lane == 0) sh[w] = v;
    __syncthreads();
    float r = sh[0] + sh[1] + sh[2] + sh[3];
    __syncthreads();
    return r;
}
__global__ void k_ln_a(const float* __restrict__ mh_b, const float* __restrict__ ln_g,
                       const float* __restrict__ ln_b) {
    int l = blockIdx.y;
    size_t row = blockIdx.x;
    const float* xr = g_x + row * EDIM;
    const float* tr = g_t1 + ((size_t)l * MROWS + row) * EDIM;
    const float* mb = mh_b + (size_t)l * EDIM;
    int base = threadIdx.x * 4;
    float v[4]; float s = 0.f;
    #pragma unroll
    for (int j = 0; j < 4; j++) { v[j] = xr[base+j] + tr[base+j] + mb[base+j]; s += v[j]; }
    float mean = block_reduce128(s) * (1.f / EDIM);
    float s2 = 0.f;
    #pragma unroll
    for (int j = 0; j < 4; j++) { float d = v[j] - mean; s2 += d * d; }
    float var = block_reduce128(s2) * (1.f / EDIM);
    float inv = rsqrtf(var + 1e-5f);
    const float* g = ln_g + (size_t)l * EDIM;
    const float* b = ln_b + (size_t)l * EDIM;
    size_t o = ((size_t)l * MROWS + row) * EDIM + base;
    #pragma unroll
    for (int j = 0; j < 4; j++) {
        float r = (v[j] - mean) * inv * g[base+j] + b[base+j];
        g_a[o+j] = r;
        g_af[o+j] = __float2half_rn(r);
    }
}
__global__ void k_ln_cat(const float* __restrict__ ln_g, const float* __restrict__ ln_b) {
    int l = blockIdx.y;
    size_t row = blockIdx.x;
    const float* tr = g_t1 + ((size_t)l * MROWS + row) * EDIM;
    const float* ar = g_a + ((size_t)l * MROWS + row) * EDIM;
    int base = threadIdx.x * 4;
    float v[4]; float s = 0.f;
    #pragma unroll
    for (int j = 0; j < 4; j++) { v[j] = tr[base+j] + ar[base+j]; s += v[j]; }
    float mean = block_reduce128(s) * (1.f / EDIM);
    float s2 = 0.f;
    #pragma unroll
    for (int j = 0; j < 4; j++) { float d = v[j] - mean; s2 += d * d; }
    float var = block_reduce128(s2) * (1.f / EDIM);
    float inv = rsqrtf(var + 1e-5f);
    const float* g = ln_g + (size_t)l * EDIM;
    const float* b = ln_b + (size_t)l * EDIM;
    size_t o = row * CATL + (size_t)l * EDIM + base;
    #pragma unroll
    for (int j = 0; j < 4; j++) {
        float r = (v[j] - mean) * inv * g[base+j] + b[base+j];
        g_catf[o+j] = __float2half_rn(r);
    }
}

// ---------------- launch ----------------------------------------------------------
extern "C" void kernel_launch(void* const* d_in, const int* in_sizes, int n_in,
                              void* d_out, int out_size) {
    (void)n_in; (void)out_size;
    const int*   inputs = (const int*)d_in[0];
    const float* emb_w  = (const float*)d_in[1];
    const float* Wq     = (const float*)d_in[2];
    const float* Wk     = (const float*)d_in[3];
    const float* Wv     = (const float*)d_in[4];
    const float *mh_w, *mh_b;
    if (in_sizes[5] == NL * EDIM) { mh_b = (const float*)d_in[5]; mh_w = (const float*)d_in[6]; }
    else                          { mh_w = (const float*)d_in[5]; mh_b = (const float*)d_in[6]; }
    const float* l1_w = (const float*)d_in[7];
    const float* l1_b = (const float*)d_in[8];
    const float* l2_w = (const float*)d_in[9];
    const float* l2_b = (const float*)d_in[10];
    const float* l3_w = (const float*)d_in[11];
    const float* l3_b = (const float*)d_in[12];
    const float* ln_g = (const float*)d_in[13];
    const float* ln_b = (const float*)d_in[14];
    const float* out_w = (const float*)d_in[15];
    const float* out_b = (const float*)d_in[16];
    float* out = (float*)d_out;

    k_pvec<<<1, 512>>>();
    k_embed<<<MROWS, 128>>>(inputs, emb_w);
    k_tconvW<<<dim3(EDIM/64, EDIM/64, LHN), 256>>>(Wq, 0, EDIM, EDIM);
    k_tconvW<<<dim3(EDIM/64, EDIM/64, LHN), 256>>>(Wk, 1, EDIM, EDIM);
    k_tconvW<<<dim3(EDIM/64, EDIM/64, LHN), 256>>>(Wv, 2, EDIM, EDIM);
    tc_qkv<<<dim3(EDIM/128, MROWS/128, 3*LHN), 256>>>();
    tc_score<<<dim3(SEQ/128, SEQ/128, LHN*BATCH), 256>>>();
    k_colsum<<<dim3(SEQ/256, LHN*BATCH), 256>>>();
    k_tconvW_vs<<<dim3(EDIM/64, SEQ/64, LHN*BATCH), 256>>>();
    tc_attnout<<<dim3(EDIM/128, SEQ/128, LHN*BATCH), 256>>>();
    k_tconvW<<<dim3(EDIM/64, CATH/64, NL), 256>>>(mh_w, 4, CATH, EDIM);
    tc_mh<<<dim3(EDIM/128, MROWS/128, NL), 256>>>();
    k_ln_a<<<dim3(MROWS, NL), 128>>>(mh_b, ln_g, ln_b);
    k_w12<<<dim3(4,4,NL), 256>>>(l1_w, l2_w);
    k_w123<<<dim3(4,4,NL), 256>>>(l3_w);
    k_bfold1<<<NL, EDIM>>>(l1_b, l2_w, l2_b);
    k_bfold2<<<NL, EDIM>>>(l3_w, l3_b);
    k_tconvW_123<<<dim3(EDIM/64, EDIM/64, NL), 256>>>();
    tc_lin<<<dim3(EDIM/128, MROWS/128, NL), 256>>>();
    k_ln_cat<<<dim3(MROWS, NL), 128>>>(ln_g, ln_b);
    k_conv<<<(int)(((size_t)CATL*VOCAB/8 + 255)/256), 256>>>(out_w, 3, (size_t)CATL*VOCAB);
    tc_final<<<dim3(MROWS/128, VOCAB/128, 1), 256>>>(out_b, out);
}